// round 4
// baseline (speedup 1.0000x reference)
#include <cuda_runtime.h>
#include <math.h>

#define B 32
#define L 200
#define DIM 36
#define ET 128
#define NH 64

#define OFF_OUT_TE 0
#define OFF_OUT1   (B*ET*DIM)
#define OFF_LOGITS (2*B*ET*DIM)
#define OFF_SXG    (OFF_LOGITS + B*2)
#define OFF_SOUT   (OFF_SXG + B*DIM*DIM)
#define OFF_QP     (OFF_SOUT + B*DIM*DIM)

typedef unsigned long long ull;

__device__ float g_qk[ET*ET];
__device__ float g_qkb[ET];
__device__ float g_emb[B*L*ET];
__device__ float g_E[B*ET*L];
__device__ float g_E2[B*ET*L];
__device__ float2 g_Y2[B*L*54];
__device__ float g_GI[B*ET*192];
__device__ float g_hfin[B*NH];

__device__ __forceinline__ ull pk2(float lo, float hi) {
    ull r; asm("mov.b64 %0, {%1,%2};" : "=l"(r) : "f"(lo), "f"(hi)); return r;
}
__device__ __forceinline__ void ffma2(ull& d, ull a, ull b) {
    asm("fma.rn.f32x2 %0, %1, %2, %0;" : "+l"(d) : "l"(a), "l"(b));
}

// ---- fused: key time embeddings + integrand Y build ----
__global__ void k_pre(const float* __restrict__ ts, const float* __restrict__ pw,
                      const float* __restrict__ pb, const float* __restrict__ tw,
                      const float* __restrict__ tb, const float* __restrict__ x) {
    if (blockIdx.x < 3200) {
        int idx = blockIdx.x*256 + threadIdx.x;       // over B*L*ET
        int bl = idx >> 7, j = idx & 127;
        float t = ts[bl];
        g_emb[idx] = (j == 0) ? fmaf(t, tw[0], tb[0]) : sinf(fmaf(t, pw[j-1], pb[j-1]));
    } else {
        int idx = (blockIdx.x - 3200)*256 + threadIdx.x;  // over B*L*108 = 691200
        int b = idx / 21600, rem = idx % 21600;
        int l = rem / 108, c = rem % 108;
        const float* xr = x + (b*L + l)*72;
        float v = (c < 72) ? xr[c] * xr[36 + (c % 36)] : xr[c - 36];
        ((float*)g_Y2)[idx] = v;
    }
}

// ---- qk[r][j] = sum_d q[r,d]*kw[d,j]; qkb[r] = q[r]·kb; passthrough qp ----
__global__ void k_qk(const float* __restrict__ qp, const float* __restrict__ pw,
                     const float* __restrict__ pb, const float* __restrict__ tw,
                     const float* __restrict__ tb, const float* __restrict__ qw,
                     const float* __restrict__ qb, const float* __restrict__ kw,
                     const float* __restrict__ kb, float* __restrict__ out) {
    int r = blockIdx.x, j = threadIdx.x;
    __shared__ float e[ET], qr[ET];
    float t = qp[r];
    e[j] = (j == 0) ? fmaf(t, tw[0], tb[0]) : sinf(fmaf(t, pw[j-1], pb[j-1]));
    if (j == 0) out[OFF_QP + r] = t;
    __syncthreads();
    float a = qb[j];
    #pragma unroll 8
    for (int d = 0; d < ET; d++) a = fmaf(qw[j*ET + d], e[d], a);
    qr[j] = a;
    __syncthreads();
    float a2 = 0.f;
    #pragma unroll 8
    for (int d = 0; d < ET; d++) a2 = fmaf(qr[d], kw[d*ET + j], a2);
    g_qk[r*ET + j] = a2;
    if (j == 0) {
        float s = 0.f;
        for (int d = 0; d < ET; d++) s = fmaf(qr[d], kb[d], s);
        g_qkb[r] = s;
    }
}

// ---- E[b,q,l] = exp(score - rowmax); also E2 = E*rand. qtile=8, grid (16,B), 128 thr ----
__global__ void __launch_bounds__(128) k_escore(const int* __restrict__ rm) {
    int q0 = blockIdx.x * 8, b = blockIdx.y, tid = threadIdx.x;
    int wy = tid >> 5, lane = tid & 31;
    __shared__ float qks[8*ET];     // 4KB
    __shared__ float ec[224*33];    // 29.5KB
    for (int i = tid; i < 8*ET; i += 128) qks[i] = g_qk[q0*ET + i];
    float acc[2][7];
    #pragma unroll
    for (int a = 0; a < 2; a++)
        #pragma unroll
        for (int c = 0; c < 7; c++) acc[a][c] = 0.f;
    for (int j0 = 0; j0 < ET; j0 += 32) {
        __syncthreads();
        for (int i = tid; i < 224*32; i += 128) {
            int row = i >> 5, col = i & 31;
            ec[row*33 + col] = (row < L) ? g_emb[(b*L + row)*ET + j0 + col] : 0.f;
        }
        __syncthreads();
        #pragma unroll 4
        for (int j = 0; j < 32; j++) {
            float rq0 = qks[(wy*2)*ET + j0 + j];
            float rq1 = qks[(wy*2 + 1)*ET + j0 + j];
            #pragma unroll
            for (int li = 0; li < 7; li++) {
                float ev = ec[(lane + 32*li)*33 + j];
                acc[0][li] = fmaf(rq0, ev, acc[0][li]);
                acc[1][li] = fmaf(rq1, ev, acc[1][li]);
            }
        }
    }
    float rl[7];
    #pragma unroll
    for (int li = 0; li < 7; li++) {
        int l = lane + 32*li;
        rl[li] = (l < L) ? (float)rm[b*L + l] : 0.f;
    }
    const float inv = 0.08838834764831845f;
    #pragma unroll
    for (int qi = 0; qi < 2; qi++) {
        int q = q0 + wy*2 + qi;
        float qkbv = g_qkb[q], s[7], m = -1e30f;
        #pragma unroll
        for (int li = 0; li < 7; li++) {
            int l = lane + 32*li;
            s[li] = (acc[qi][li] + qkbv) * inv;
            if (l < L) m = fmaxf(m, s[li]);
        }
        #pragma unroll
        for (int off = 16; off; off >>= 1) m = fmaxf(m, __shfl_xor_sync(0xffffffffu, m, off));
        #pragma unroll
        for (int li = 0; li < 7; li++) {
            int l = lane + 32*li;
            if (l < L) {
                float E = __expf(s[li] - m);
                g_E [(b*ET + q)*L + l] = E;
                g_E2[(b*ET + q)*L + l] = E * rl[li];
            }
        }
    }
}

// ---- masked-attention GEMM: grid (8, B, 2masks), 256 thr, FFMA2 inner ----
__global__ void __launch_bounds__(256) k_mta(const float* __restrict__ ow, const float* __restrict__ ob,
                                             const float* __restrict__ wih, const float* __restrict__ bih,
                                             float* __restrict__ out) {
    int q0 = blockIdx.x * 16, b = blockIdx.y, z = blockIdx.z, tid = threadIdx.x;
    int tg = tid >> 5, tc = tid & 31;
    const float* Esrc = z ? g_E2 : g_E;
    __shared__ __align__(16) float buf[6352];
    float* ys = buf;            // [32][128] floats (108 used)
    float* Es = buf + 4096;     // [16][33]
    float* os = buf + 4624;     // [16][72]
    float* ot = buf + 5776;     // [16][36]
    // zero ys pad pairs 54..63 once
    for (int i = tid; i < 32*10; i += 256) {
        int l = i / 10, p = 54 + i % 10;
        ((float2*)ys)[l*64 + p] = make_float2(0.f, 0.f);
    }
    ull a00 = 0, a01 = 0, a10 = 0, a11 = 0;
    for (int l0 = 0; l0 < L; l0 += 32) {
        __syncthreads();
        for (int i = tid; i < 32*54; i += 256) {
            int l = i / 54, c = i % 54, gl = l0 + l;
            ((float2*)ys)[l*64 + c] = (gl < L) ? g_Y2[(b*L + gl)*54 + c] : make_float2(0.f, 0.f);
        }
        for (int i = tid; i < 16*32; i += 256) {
            int q = i >> 5, l = i & 31, gl = l0 + l;
            Es[q*33 + l] = (gl < L) ? Esrc[(b*ET + q0 + q)*L + gl] : 0.f;
        }
        __syncthreads();
        #pragma unroll 8
        for (int l = 0; l < 32; l++) {
            float e0 = Es[(tg*2)*33 + l];
            float e1 = Es[(tg*2 + 1)*33 + l];
            ull ee0 = pk2(e0, e0), ee1 = pk2(e1, e1);
            ull ya = *(const ull*)&ys[l*128 + 2*tc];
            ull yb = *(const ull*)&ys[l*128 + 2*tc + 64];
            ffma2(a00, ee0, ya); ffma2(a01, ee0, yb);
            ffma2(a10, ee1, ya); ffma2(a11, ee1, yb);
        }
    }
    __syncthreads();
    float* Cs = ys;   // [16][128], overlays dead ys
    *(ull*)&Cs[(tg*2)*128 + 2*tc]        = a00;
    *(ull*)&Cs[(tg*2)*128 + 2*tc + 64]   = a01;
    *(ull*)&Cs[(tg*2+1)*128 + 2*tc]      = a10;
    *(ull*)&Cs[(tg*2+1)*128 + 2*tc + 64] = a11;
    __syncthreads();
    for (int i = tid; i < 16*72; i += 256) {
        int q = i / 72, d = i % 72;
        os[i] = Cs[q*128 + d] / Cs[q*128 + 72 + (d % 36)];
    }
    __syncthreads();
    for (int i = tid; i < 16*36; i += 256) {
        int q = i / 36, dd = i % 36;
        float a = ob[dd];
        #pragma unroll 8
        for (int d = 0; d < 72; d++) a = fmaf(os[q*72 + d], ow[dd*72 + d], a);
        out[(z ? OFF_OUT1 : OFF_OUT_TE) + (b*ET + q0 + q)*DIM + dd] = a;
        ot[q*36 + dd] = a;
    }
    if (z == 0) {
        __syncthreads();
        for (int i = tid; i < 16*192; i += 256) {
            int q = i / 192, j = i % 192;
            float a = bih[j];
            #pragma unroll 4
            for (int d = 0; d < 36; d++) a = fmaf(ot[q*36 + d], wih[j*36 + d], a);
            g_GI[(b*ET + q0 + q)*192 + j] = a;
        }
    }
}

// ---- gram matrices, split: blockIdx.y 0 -> sout(out_te,128), 1 -> sx_g(x,200) ----
__global__ void __launch_bounds__(288) k_gram(const float* __restrict__ x, float* __restrict__ out) {
    int b = blockIdx.x, which = blockIdx.y, tid = threadIdx.x;
    __shared__ float sm[L*36];
    int n = which ? L : ET;
    if (which == 0) {
        for (int i = tid; i < ET*36; i += 288) sm[i] = out[OFF_OUT_TE + b*ET*36 + i];
    } else {
        for (int i = tid; i < L*36; i += 288) sm[i] = x[(b*L + i/36)*72 + i%36];
    }
    __syncthreads();
    int tile = tid % 144, half = tid / 144;
    int d0 = (tile / 12) * 3, e0 = (tile % 12) * 3;
    int i0 = half * (n >> 1), i1 = i0 + (n >> 1);
    float a[3][3];
    #pragma unroll
    for (int i = 0; i < 3; i++)
        #pragma unroll
        for (int j = 0; j < 3; j++) a[i][j] = 0.f;
    for (int r = i0; r < i1; r++) {
        float u0 = sm[r*36+d0], u1 = sm[r*36+d0+1], u2 = sm[r*36+d0+2];
        float v0 = sm[r*36+e0], v1 = sm[r*36+e0+1], v2 = sm[r*36+e0+2];
        a[0][0]=fmaf(u0,v0,a[0][0]); a[0][1]=fmaf(u0,v1,a[0][1]); a[0][2]=fmaf(u0,v2,a[0][2]);
        a[1][0]=fmaf(u1,v0,a[1][0]); a[1][1]=fmaf(u1,v1,a[1][1]); a[1][2]=fmaf(u1,v2,a[1][2]);
        a[2][0]=fmaf(u2,v0,a[2][0]); a[2][1]=fmaf(u2,v1,a[2][1]); a[2][2]=fmaf(u2,v2,a[2][2]);
    }
    __syncthreads();
    float* pr = sm;
    if (half == 1) {
        #pragma unroll
        for (int i = 0; i < 3; i++)
            #pragma unroll
            for (int j = 0; j < 3; j++) pr[tile*9 + i*3 + j] = a[i][j];
    }
    __syncthreads();
    if (half == 0) {
        int off = which ? OFF_SXG : OFF_SOUT;
        #pragma unroll
        for (int i = 0; i < 3; i++)
            #pragma unroll
            for (int j = 0; j < 3; j++) {
                float v = a[i][j] + pr[tile*9 + i*3 + j];
                float sg = 1.f / (1.f + expf(-v));
                out[off + b*1296 + (d0+i)*36 + (e0+j)] = which ? rintf(sg) : sg;
            }
    }
}

// ---- GRU scan: one block per batch, 192 threads, gi prefetch ----
__global__ void __launch_bounds__(192, 1) k_gru(const float* __restrict__ whh,
                                                const float* __restrict__ bhh_p) {
    int b = blockIdx.x, j = threadIdx.x;
    __shared__ float h[2][64];
    __shared__ float s[192];
    __shared__ float gin[64];
    float w[64];
    #pragma unroll
    for (int i = 0; i < 64; i++) w[i] = whh[j*64 + i];
    float bhh = bhh_p[j];
    if (j < 64) { h[0][j] = 0.f; h[1][j] = 0.f; }
    const float* gi = g_GI + b*ET*192;
    float gcur = gi[j];
    __syncthreads();
    int p = 0;
    for (int t = 0; t < ET; t++) {
        float gnext = (t < ET-1) ? gi[(t+1)*192 + j] : 0.f;
        float a0 = bhh, a1 = 0.f, a2 = 0.f, a3 = 0.f, a4 = 0.f, a5 = 0.f, a6 = 0.f, a7 = 0.f;
        const float4* h4 = (const float4*)h[p];
        #pragma unroll
        for (int i = 0; i < 8; i++) {
            float4 u = h4[2*i], v = h4[2*i + 1];
            a0 = fmaf(w[8*i],   u.x, a0);
            a1 = fmaf(w[8*i+1], u.y, a1);
            a2 = fmaf(w[8*i+2], u.z, a2);
            a3 = fmaf(w[8*i+3], u.w, a3);
            a4 = fmaf(w[8*i+4], v.x, a4);
            a5 = fmaf(w[8*i+5], v.y, a5);
            a6 = fmaf(w[8*i+6], v.z, a6);
            a7 = fmaf(w[8*i+7], v.w, a7);
        }
        float gh = ((a0 + a1) + (a2 + a3)) + ((a4 + a5) + (a6 + a7));
        if (j < 128) s[j] = gcur + gh;
        else { s[j] = gh; gin[j - 128] = gcur; }
        __syncthreads();
        if (j < 64) {
            float r = __fdividef(1.f, 1.f + __expf(-s[j]));
            float z = __fdividef(1.f, 1.f + __expf(-s[64 + j]));
            float narg = fmaf(r, s[128 + j], gin[j]);
            float e2 = __expf(2.f * narg);
            float n = 1.f - __fdividef(2.f, e2 + 1.f);
            h[p ^ 1][j] = fmaf(z, h[p][j] - n, n);
        }
        __syncthreads();
        gcur = gnext;
        p ^= 1;
    }
    if (j < 64) g_hfin[b*64 + j] = h[p][j];
}

// ---- classifier head: single block, 256 threads ----
__global__ void k_cls(const float* __restrict__ si, const float* __restrict__ stw,
                      const float* __restrict__ stb, const float* __restrict__ c1w,
                      const float* __restrict__ c1b, const float* __restrict__ bng,
                      const float* __restrict__ bnb, const float* __restrict__ c2w,
                      const float* __restrict__ c2b, float* __restrict__ out) {
    __shared__ float ci[32*72];
    __shared__ float zs[32*72];
    __shared__ float mus[72], ivs[72];
    int tid = threadIdx.x;
    for (int i = tid; i < 32*72; i += 256) {
        int b = i / 72, j = i % 72;
        float v;
        if (j < 64) v = g_hfin[b*64 + j];
        else {
            int jj = j - 64;
            float a = stb[jj];
            #pragma unroll
            for (int s = 0; s < 9; s++) a = fmaf(si[b*9 + s], stw[jj*9 + s], a);
            v = a;
        }
        ci[i] = v;
    }
    __syncthreads();
    for (int i = tid; i < 32*72; i += 256) {
        int b = i / 72, j = i % 72;
        float a = c1b[j];
        #pragma unroll 8
        for (int d = 0; d < 72; d++) a = fmaf(ci[b*72 + d], c1w[j*72 + d], a);
        zs[i] = a;
    }
    __syncthreads();
    if (tid < 72) {
        float mu = 0.f;
        for (int b = 0; b < 32; b++) mu += zs[b*72 + tid];
        mu *= (1.f / 32.f);
        float m2 = 0.f;
        for (int b = 0; b < 32; b++) { float d = zs[b*72 + tid] - mu; m2 = fmaf(d, d, m2); }
        mus[tid] = mu;
        ivs[tid] = rsqrtf(m2 * (1.f / 32.f) + 1e-5f);
    }
    __syncthreads();
    for (int i = tid; i < 32*72; i += 256) {
        int j = i % 72;
        float zn = (zs[i] - mus[j]) * ivs[j] * bng[j] + bnb[j];
        zs[i] = zn * 0.5f * (1.f + erff(zn * 0.7071067811865475f));
    }
    __syncthreads();
    if (tid < 64) {
        int b = tid >> 1, c = tid & 1;
        float a = c2b[c];
        #pragma unroll 8
        for (int d = 0; d < 72; d++) a = fmaf(zs[b*72 + d], c2w[c*72 + d], a);
        out[OFF_LOGITS + b*2 + c] = a;
    }
}

extern "C" void kernel_launch(void* const* d_in, const int* in_sizes, int n_in,
                              void* d_out, int out_size) {
    const float* x    = (const float*)d_in[0];
    const float* ts   = (const float*)d_in[1];
    const float* si   = (const float*)d_in[2];
    const float* qp   = (const float*)d_in[3];
    const float* pw   = (const float*)d_in[4];
    const float* pb   = (const float*)d_in[5];
    const float* tw   = (const float*)d_in[6];
    const float* tb   = (const float*)d_in[7];
    const float* qw   = (const float*)d_in[8];
    const float* qb   = (const float*)d_in[9];
    const float* kw   = (const float*)d_in[10];
    const float* kb   = (const float*)d_in[11];
    const float* ow   = (const float*)d_in[12];
    const float* ob   = (const float*)d_in[13];
    const float* wih  = (const float*)d_in[14];
    const float* whh  = (const float*)d_in[15];
    const float* bih  = (const float*)d_in[16];
    const float* bhh  = (const float*)d_in[17];
    const float* stw  = (const float*)d_in[18];
    const float* stb  = (const float*)d_in[19];
    const float* c1w  = (const float*)d_in[20];
    const float* c1b  = (const float*)d_in[21];
    const float* bng  = (const float*)d_in[22];
    const float* bnb  = (const float*)d_in[23];
    const float* c2w  = (const float*)d_in[24];
    const float* c2b  = (const float*)d_in[25];
    const int*   rm   = (const int*)d_in[26];
    float* out = (float*)d_out;

    k_pre<<<5900, 256>>>(ts, pw, pb, tw, tb, x);
    k_qk<<<ET, ET>>>(qp, pw, pb, tw, tb, qw, qb, kw, kb, out);
    k_escore<<<dim3(16, B), 128>>>(rm);
    k_mta<<<dim3(8, B, 2), 256>>>(ow, ob, wih, bih, out);
    k_gram<<<dim3(B, 2), 288>>>(x, out);
    k_gru<<<B, 192>>>(whh, bhh);
    k_cls<<<1, 256>>>(si, stw, stb, c1w, c1b, bng, bnb, c2w, c2b, out);
}

// round 5
// speedup vs baseline: 1.4056x; 1.4056x over previous
#include <cuda_runtime.h>
#include <math.h>

#define B 32
#define L 200
#define DIM 36
#define ET 128
#define NH 64

#define OFF_OUT_TE 0
#define OFF_OUT1   (B*ET*DIM)
#define OFF_LOGITS (2*B*ET*DIM)
#define OFF_SXG    (OFF_LOGITS + B*2)
#define OFF_SOUT   (OFF_SXG + B*DIM*DIM)
#define OFF_QP     (OFF_SOUT + B*DIM*DIM)

typedef unsigned long long ull;

__device__ ull   g_qk2[ET*ET];          // dup-packed, pre-scaled qk
__device__ float g_qkb[ET];             // pre-scaled
__device__ float g_embT[B*ET*256];      // [b][j][l] transposed, l padded to 256 w/ zeros
__device__ float g_E[B*ET*L];
__device__ float g_Y[B*L*108];          // integrand [x*obs | obs]
__device__ float g_GI[B*ET*192];
__device__ float g_hfin[B*NH];

__device__ __forceinline__ ull pk2(float lo, float hi) {
    ull r; asm("mov.b64 %0, {%1,%2};" : "=l"(r) : "f"(lo), "f"(hi)); return r;
}
__device__ __forceinline__ void ffma2(ull& d, ull a, ull b) {
    asm("fma.rn.f32x2 %0, %1, %2, %0;" : "+l"(d) : "l"(a), "l"(b));
}
__device__ __forceinline__ void cpa16(unsigned s, const void* g) {
    asm volatile("cp.async.cg.shared.global [%0], [%1], 16;" :: "r"(s), "l"(g));
}
__device__ __forceinline__ void cpa16z(unsigned s, const void* g, int sz) {
    asm volatile("cp.async.cg.shared.global [%0], [%1], 16, %2;" :: "r"(s), "l"(g), "r"(sz));
}
#define CPCOMMIT() asm volatile("cp.async.commit_group;")
#define CPWAIT0()  asm volatile("cp.async.wait_group 0;")

// ---- k_pre: embT (transposed+padded) + Y integrand ----
#define N1 (B*ET*L)       // 819200
#define N2 (B*ET*56)      // 229376 pad zeros
#define N3 (B*L*108)      // 691200
__global__ void k_pre(const float* __restrict__ ts, const float* __restrict__ pw,
                      const float* __restrict__ pb, const float* __restrict__ tw,
                      const float* __restrict__ tb, const float* __restrict__ x) {
    int idx = blockIdx.x*256 + threadIdx.x;
    if (idx < N1) {
        int b = idx / (ET*L), r = idx % (ET*L);
        int j = r / L, l = r % L;
        float t = ts[b*L + l];
        float v = (j == 0) ? fmaf(t, tw[0], tb[0]) : __sinf(fmaf(t, pw[j-1], pb[j-1]));
        g_embT[(b*ET + j)*256 + l] = v;
    } else if (idx < N1 + N2) {
        int k = idx - N1;
        int bj = k / 56, o = k % 56;
        g_embT[bj*256 + 200 + o] = 0.f;
    } else {
        int k = idx - N1 - N2;
        int b = k / 21600, rem = k % 21600;
        int l = rem / 108, c = rem % 108;
        const float* xr = x + (b*L + l)*72;
        g_Y[k] = (c < 72) ? xr[c] * xr[36 + (c % 36)] : xr[c - 36];
    }
}

// ---- k_qk: qk2[r][j] = dup((q[r]·kw_col_j)*inv); qkb pre-scaled; passthrough qp ----
__global__ void k_qk(const float* __restrict__ qp, const float* __restrict__ pw,
                     const float* __restrict__ pb, const float* __restrict__ tw,
                     const float* __restrict__ tb, const float* __restrict__ qw,
                     const float* __restrict__ qb, const float* __restrict__ kw,
                     const float* __restrict__ kb, float* __restrict__ out) {
    int r = blockIdx.x, j = threadIdx.x;
    __shared__ float e[ET], qr[ET];
    float t = qp[r];
    e[j] = (j == 0) ? fmaf(t, tw[0], tb[0]) : __sinf(fmaf(t, pw[j-1], pb[j-1]));
    if (j == 0) out[OFF_QP + r] = t;
    __syncthreads();
    float a = qb[j];
    #pragma unroll 8
    for (int d = 0; d < ET; d++) a = fmaf(qw[j*ET + d], e[d], a);
    qr[j] = a;
    __syncthreads();
    const float inv = 0.08838834764831845f;
    float a2 = 0.f;
    #pragma unroll 8
    for (int d = 0; d < ET; d++) a2 = fmaf(qr[d], kw[d*ET + j], a2);
    float v = a2 * inv;
    g_qk2[r*ET + j] = pk2(v, v);
    if (j == 0) {
        float s = 0.f;
        for (int d = 0; d < ET; d++) s = fmaf(qr[d], kb[d], s);
        g_qkb[r] = s * inv;
    }
}

// ---- k_escore: E = exp(score - rowmax), FFMA2 over l-pairs, cp.async pipelined ----
// grid (8, B), 128 threads; qtile 16 (4 q per warp)
__global__ void __launch_bounds__(128) k_escore() {
    int q0 = blockIdx.x * 16, b = blockIdx.y, tid = threadIdx.x;
    int w = tid >> 5, tc = tid & 31;
    __shared__ __align__(16) ull qs[16*128];      // 16KB
    __shared__ __align__(16) ull et[2][16*128];   // 32KB
    unsigned qs_s = (unsigned)__cvta_generic_to_shared(qs);
    unsigned et_s0 = (unsigned)__cvta_generic_to_shared(et[0]);
    unsigned et_s1 = (unsigned)__cvta_generic_to_shared(et[1]);

    // stage qk2 tile + first embT chunk
    {
        const char* src = (const char*)(g_qk2 + q0*ET);
        for (int i = tid; i < 1024; i += 128) cpa16(qs_s + i*16, src + i*16);
        const char* es = (const char*)g_embT + (size_t)(b*ET)*1024;
        for (int i = tid; i < 1024; i += 128) cpa16(et_s0 + i*16, es + i*16);
        CPCOMMIT();
    }
    ull acc[4][4];
    #pragma unroll
    for (int a = 0; a < 4; a++)
        #pragma unroll
        for (int c = 0; c < 4; c++) acc[a][c] = 0;

    for (int ch = 0; ch < 8; ch++) {
        CPWAIT0();
        __syncthreads();
        if (ch < 7) {
            unsigned dst = (ch & 1) ? et_s0 : et_s1;   // next buffer = (ch+1)&1
            const char* es = (const char*)g_embT + (size_t)(b*ET + (ch+1)*16)*1024;
            for (int i = tid; i < 1024; i += 128) cpa16(dst + i*16, es + i*16);
            CPCOMMIT();
        }
        const ull* etb = et[ch & 1];
        #pragma unroll
        for (int jj = 0; jj < 16; jj++) {
            int jg = ch*16 + jj;
            ull qv[4], ev[4];
            #pragma unroll
            for (int qi = 0; qi < 4; qi++) qv[qi] = qs[(w*4 + qi)*128 + jg];
            #pragma unroll
            for (int li = 0; li < 4; li++) ev[li] = etb[jj*128 + tc + 32*li];
            #pragma unroll
            for (int qi = 0; qi < 4; qi++)
                #pragma unroll
                for (int li = 0; li < 4; li++) ffma2(acc[qi][li], qv[qi], ev[li]);
        }
    }
    // epilogue: rowmax + exp + store E pairs
    #pragma unroll
    for (int qi = 0; qi < 4; qi++) {
        int q = q0 + w*4 + qi;
        float qkbv = g_qkb[q];
        float slo[4], shi[4];
        float m = -1e30f;
        #pragma unroll
        for (int li = 0; li < 4; li++) {
            float2 f = *(float2*)&acc[qi][li];
            slo[li] = f.x + qkbv; shi[li] = f.y + qkbv;
            if (li < 3 || tc < 4) m = fmaxf(m, fmaxf(slo[li], shi[li]));
        }
        #pragma unroll
        for (int off = 16; off; off >>= 1) m = fmaxf(m, __shfl_xor_sync(0xffffffffu, m, off));
        float* base = g_E + (b*ET + q)*L;
        #pragma unroll
        for (int li = 0; li < 4; li++) {
            int p = tc + 32*li;
            if (li < 3 || tc < 4)
                *(float2*)(base + 2*p) = make_float2(__expf(slo[li] - m), __expf(shi[li] - m));
        }
    }
}

// ---- k_mta: fused-mask attention GEMM, cp.async double-buffered, FFMA2 ----
// grid (8, B), 256 threads
__global__ void __launch_bounds__(256) k_mta(const int* __restrict__ rm,
                                             const float* __restrict__ ow, const float* __restrict__ ob,
                                             const float* __restrict__ wih, const float* __restrict__ bih,
                                             float* __restrict__ out) {
    int q0 = blockIdx.x * 16, b = blockIdx.y, tid = threadIdx.x;
    int tg = tid >> 5, tc = tid & 31;
    __shared__ __align__(16) float buf[9280];
    float* ys  = buf;            // [2][32][128]  8192 floats
    float* Es  = buf + 8192;     // [2][16][32]   1024 floats
    int*   rmI = (int*)(buf + 9216);  // [2][32]
    unsigned ys_s  = (unsigned)__cvta_generic_to_shared(ys);
    unsigned Es_s  = (unsigned)__cvta_generic_to_shared(Es);
    unsigned rm_s  = (unsigned)__cvta_generic_to_shared(rmI);

    // zero ys pad cols (108..127) both buffers — cp.async never writes them
    for (int i = tid; i < 2*32*20; i += 256) {
        int bu = i / 640, r = (i % 640) / 20, c = 108 + i % 20;
        ys[bu*4096 + r*128 + c] = 0.f;
    }

    // stage tile 0 into buffer 0
    {
        for (int i = tid; i < 864; i += 256) {
            int row = i / 27, ck = i % 27;
            cpa16(ys_s + row*512 + ck*16, (const char*)(g_Y + (b*L + row)*108) + ck*16);
        }
        if (tid < 128) {
            int q = tid / 8, ck = tid % 8;
            cpa16(Es_s + q*128 + ck*16, (const char*)(g_E + (b*ET + q0 + q)*L) + ck*16);
        }
        if (tid < 8) cpa16(rm_s + tid*16, (const char*)(rm + b*L) + tid*16);
        CPCOMMIT();
    }

    ull a00=0,a01=0,a10=0,a11=0, b00=0,b01=0,b10=0,b11=0;
    for (int t = 0; t < 7; t++) {
        CPWAIT0();
        __syncthreads();
        if (t < 6) {
            int l0 = (t+1)*32, bu = (t+1) & 1;
            for (int i = tid; i < 864; i += 256) {
                int row = i / 27, ck = i % 27, gl = l0 + row;
                if (gl < L)
                    cpa16(ys_s + bu*16384 + row*512 + ck*16,
                          (const char*)(g_Y + (b*L + gl)*108) + ck*16);
            }
            if (tid < 128) {
                int q = tid / 8, ck = tid % 8;
                int rem = (L - l0)*4 - ck*16;
                int sz = rem < 0 ? 0 : (rem > 16 ? 16 : rem);
                cpa16z(Es_s + bu*2048 + q*128 + ck*16,
                       (const char*)(g_E + (b*ET + q0 + q)*L + l0) + ck*16, sz);
            }
            if (tid < 8) {
                int rem = (L - l0)*4 - tid*16;
                int sz = rem < 0 ? 0 : (rem > 16 ? 16 : rem);
                cpa16z(rm_s + bu*128 + tid*16, (const char*)(rm + b*L + l0) + tid*16, sz);
            }
            CPCOMMIT();
        }
        const float* yb_ = ys + (t & 1)*4096;
        const float* Eb_ = Es + (t & 1)*512;
        const int*   rb_ = rmI + (t & 1)*32;
        #pragma unroll 4
        for (int l = 0; l < 32; l++) {
            float e0 = Eb_[(2*tg)*32 + l];
            float e1 = Eb_[(2*tg + 1)*32 + l];
            float rl = (float)rb_[l];
            float f0 = e0 * rl, f1 = e1 * rl;
            ull ee0 = pk2(e0, e0), ee1 = pk2(e1, e1);
            ull ff0 = pk2(f0, f0), ff1 = pk2(f1, f1);
            ull ya = *(const ull*)&yb_[l*128 + 2*tc];
            ull yc = *(const ull*)&yb_[l*128 + 2*tc + 64];
            ffma2(a00, ee0, ya); ffma2(a01, ee0, yc);
            ffma2(a10, ee1, ya); ffma2(a11, ee1, yc);
            ffma2(b00, ff0, ya); ffma2(b01, ff0, yc);
            ffma2(b10, ff1, ya); ffma2(b11, ff1, yc);
        }
    }
    __syncthreads();
    // epilogue overlay: Cs[16][256] (mask0 at 0..127, mask1 at 128..255)
    float* Cs = buf;            // 4096
    float* os = buf + 4096;     // [16][144] 2304
    float* ot = buf + 6400;     // [16][36]  576
    *(ull*)&Cs[(2*tg)*256 + 2*tc]         = a00;
    *(ull*)&Cs[(2*tg)*256 + 2*tc + 64]    = a01;
    *(ull*)&Cs[(2*tg)*256 + 2*tc + 128]   = b00;
    *(ull*)&Cs[(2*tg)*256 + 2*tc + 192]   = b01;
    *(ull*)&Cs[(2*tg+1)*256 + 2*tc]       = a10;
    *(ull*)&Cs[(2*tg+1)*256 + 2*tc + 64]  = a11;
    *(ull*)&Cs[(2*tg+1)*256 + 2*tc + 128] = b10;
    *(ull*)&Cs[(2*tg+1)*256 + 2*tc + 192] = b11;
    __syncthreads();
    for (int i = tid; i < 16*144; i += 256) {
        int q = i / 144, c = i % 144, m = c / 72, d = c % 72;
        os[q*144 + c] = Cs[q*256 + m*128 + d] / Cs[q*256 + m*128 + 72 + (d % 36)];
    }
    __syncthreads();
    for (int i = tid; i < 16*72; i += 256) {
        int q = i / 72, c = i % 72, m = c / 36, dd = c % 36;
        float a = ob[dd];
        #pragma unroll 8
        for (int d = 0; d < 72; d++) a = fmaf(os[q*144 + m*72 + d], ow[dd*72 + d], a);
        out[(m ? OFF_OUT1 : OFF_OUT_TE) + (b*ET + q0 + q)*DIM + dd] = a;
        if (m == 0) ot[q*36 + dd] = a;
    }
    __syncthreads();
    for (int i = tid; i < 16*192; i += 256) {
        int q = i / 192, j = i % 192;
        float a = bih[j];
        #pragma unroll 4
        for (int d = 0; d < 36; d++) a = fmaf(ot[q*36 + d], wih[j*36 + d], a);
        g_GI[(b*ET + q0 + q)*192 + j] = a;
    }
}

// ---- gram matrices ----
__global__ void __launch_bounds__(288) k_gram(const float* __restrict__ x, float* __restrict__ out) {
    int b = blockIdx.x, which = blockIdx.y, tid = threadIdx.x;
    __shared__ float sm[L*36];
    int n = which ? L : ET;
    if (which == 0) {
        for (int i = tid; i < ET*36; i += 288) sm[i] = out[OFF_OUT_TE + b*ET*36 + i];
    } else {
        for (int i = tid; i < L*36; i += 288) sm[i] = x[(b*L + i/36)*72 + i%36];
    }
    __syncthreads();
    int tile = tid % 144, half = tid / 144;
    int d0 = (tile / 12) * 3, e0 = (tile % 12) * 3;
    int i0 = half * (n >> 1), i1 = i0 + (n >> 1);
    float a[3][3];
    #pragma unroll
    for (int i = 0; i < 3; i++)
        #pragma unroll
        for (int j = 0; j < 3; j++) a[i][j] = 0.f;
    for (int r = i0; r < i1; r++) {
        float u0 = sm[r*36+d0], u1 = sm[r*36+d0+1], u2 = sm[r*36+d0+2];
        float v0 = sm[r*36+e0], v1 = sm[r*36+e0+1], v2 = sm[r*36+e0+2];
        a[0][0]=fmaf(u0,v0,a[0][0]); a[0][1]=fmaf(u0,v1,a[0][1]); a[0][2]=fmaf(u0,v2,a[0][2]);
        a[1][0]=fmaf(u1,v0,a[1][0]); a[1][1]=fmaf(u1,v1,a[1][1]); a[1][2]=fmaf(u1,v2,a[1][2]);
        a[2][0]=fmaf(u2,v0,a[2][0]); a[2][1]=fmaf(u2,v1,a[2][1]); a[2][2]=fmaf(u2,v2,a[2][2]);
    }
    __syncthreads();
    float* pr = sm;
    if (half == 1) {
        #pragma unroll
        for (int i = 0; i < 3; i++)
            #pragma unroll
            for (int j = 0; j < 3; j++) pr[tile*9 + i*3 + j] = a[i][j];
    }
    __syncthreads();
    if (half == 0) {
        int off = which ? OFF_SXG : OFF_SOUT;
        #pragma unroll
        for (int i = 0; i < 3; i++)
            #pragma unroll
            for (int j = 0; j < 3; j++) {
                float v = a[i][j] + pr[tile*9 + i*3 + j];
                float sg = 1.f / (1.f + expf(-v));
                out[off + b*1296 + (d0+i)*36 + (e0+j)] = which ? rintf(sg) : sg;
            }
    }
}

// ---- GRU scan: 1 block/batch, 192 threads, FFMA2 matvec + gi prefetch ----
__global__ void __launch_bounds__(192, 1) k_gru(const float* __restrict__ whh,
                                                const float* __restrict__ bhh_p) {
    int b = blockIdx.x, j = threadIdx.x;
    __shared__ __align__(16) float h[2][64];
    __shared__ float s[192];
    __shared__ float gin[64];
    ull wp[32];
    const ull* whh2 = (const ull*)whh;
    #pragma unroll
    for (int i = 0; i < 32; i++) wp[i] = whh2[j*32 + i];
    float bhh = bhh_p[j];
    if (j < 64) { h[0][j] = 0.f; h[1][j] = 0.f; }
    const float* gi = g_GI + b*ET*192;
    float gcur = gi[j];
    __syncthreads();
    int p = 0;
    for (int t = 0; t < ET; t++) {
        float gnext = (t < ET-1) ? gi[(t+1)*192 + j] : 0.f;
        ull a[8];
        #pragma unroll
        for (int i = 0; i < 8; i++) a[i] = 0;
        const ulonglong2* h2 = (const ulonglong2*)h[p];
        #pragma unroll
        for (int i = 0; i < 16; i++) {
            ulonglong2 hv = h2[i];
            ffma2(a[(2*i) & 7],     wp[2*i],     hv.x);
            ffma2(a[(2*i + 1) & 7], wp[2*i + 1], hv.y);
        }
        float gh = bhh;
        #pragma unroll
        for (int i = 0; i < 8; i++) {
            float2 f = *(float2*)&a[i];
            gh += f.x + f.y;
        }
        if (j < 128) s[j] = gcur + gh;
        else { s[j] = gh; gin[j - 128] = gcur; }
        __syncthreads();
        if (j < 64) {
            float r = __fdividef(1.f, 1.f + __expf(-s[j]));
            float z = __fdividef(1.f, 1.f + __expf(-s[64 + j]));
            float narg = fmaf(r, s[128 + j], gin[j]);
            float e2 = __expf(2.f * narg);
            float n = 1.f - __fdividef(2.f, e2 + 1.f);
            h[p ^ 1][j] = fmaf(z, h[p][j] - n, n);
        }
        __syncthreads();
        gcur = gnext;
        p ^= 1;
    }
    if (j < 64) g_hfin[b*64 + j] = h[p][j];
}

// ---- classifier head ----
__global__ void k_cls(const float* __restrict__ si, const float* __restrict__ stw,
                      const float* __restrict__ stb, const float* __restrict__ c1w,
                      const float* __restrict__ c1b, const float* __restrict__ bng,
                      const float* __restrict__ bnb, const float* __restrict__ c2w,
                      const float* __restrict__ c2b, float* __restrict__ out) {
    __shared__ float ci[32*72];
    __shared__ float zs[32*72];
    __shared__ float mus[72], ivs[72];
    int tid = threadIdx.x;
    for (int i = tid; i < 32*72; i += 256) {
        int b = i / 72, j = i % 72;
        float v;
        if (j < 64) v = g_hfin[b*64 + j];
        else {
            int jj = j - 64;
            float a = stb[jj];
            #pragma unroll
            for (int s = 0; s < 9; s++) a = fmaf(si[b*9 + s], stw[jj*9 + s], a);
            v = a;
        }
        ci[i] = v;
    }
    __syncthreads();
    for (int i = tid; i < 32*72; i += 256) {
        int b = i / 72, j = i % 72;
        float a = c1b[j];
        #pragma unroll 8
        for (int d = 0; d < 72; d++) a = fmaf(ci[b*72 + d], c1w[j*72 + d], a);
        zs[i] = a;
    }
    __syncthreads();
    if (tid < 72) {
        float mu = 0.f;
        for (int b = 0; b < 32; b++) mu += zs[b*72 + tid];
        mu *= (1.f / 32.f);
        float m2 = 0.f;
        for (int b = 0; b < 32; b++) { float d = zs[b*72 + tid] - mu; m2 = fmaf(d, d, m2); }
        mus[tid] = mu;
        ivs[tid] = rsqrtf(m2 * (1.f / 32.f) + 1e-5f);
    }
    __syncthreads();
    for (int i = tid; i < 32*72; i += 256) {
        int j = i % 72;
        float zn = (zs[i] - mus[j]) * ivs[j] * bng[j] + bnb[j];
        zs[i] = zn * 0.5f * (1.f + erff(zn * 0.7071067811865475f));
    }
    __syncthreads();
    if (tid < 64) {
        int b = tid >> 1, c = tid & 1;
        float a = c2b[c];
        #pragma unroll 8
        for (int d = 0; d < 72; d++) a = fmaf(zs[b*72 + d], c2w[c*72 + d], a);
        out[OFF_LOGITS + b*2 + c] = a;
    }
}

extern "C" void kernel_launch(void* const* d_in, const int* in_sizes, int n_in,
                              void* d_out, int out_size) {
    const float* x    = (const float*)d_in[0];
    const float* ts   = (const float*)d_in[1];
    const float* si   = (const float*)d_in[2];
    const float* qp   = (const float*)d_in[3];
    const float* pw   = (const float*)d_in[4];
    const float* pb   = (const float*)d_in[5];
    const float* tw   = (const float*)d_in[6];
    const float* tb   = (const float*)d_in[7];
    const float* qw   = (const float*)d_in[8];
    const float* qb   = (const float*)d_in[9];
    const float* kw   = (const float*)d_in[10];
    const float* kb   = (const float*)d_in[11];
    const float* ow   = (const float*)d_in[12];
    const float* ob   = (const float*)d_in[13];
    const float* wih  = (const float*)d_in[14];
    const float* whh  = (const float*)d_in[15];
    const float* bih  = (const float*)d_in[16];
    const float* bhh  = (const float*)d_in[17];
    const float* stw  = (const float*)d_in[18];
    const float* stb  = (const float*)d_in[19];
    const float* c1w  = (const float*)d_in[20];
    const float* c1b  = (const float*)d_in[21];
    const float* bng  = (const float*)d_in[22];
    const float* bnb  = (const float*)d_in[23];
    const float* c2w  = (const float*)d_in[24];
    const float* c2b  = (const float*)d_in[25];
    const int*   rm   = (const int*)d_in[26];
    float* out = (float*)d_out;

    k_pre<<<6796, 256>>>(ts, pw, pb, tw, tb, x);
    k_qk<<<ET, ET>>>(qp, pw, pb, tw, tb, qw, qb, kw, kb, out);
    k_escore<<<dim3(8, B), 128>>>();
    k_mta<<<dim3(8, B), 256>>>(rm, ow, ob, wih, bih, out);
    k_gram<<<dim3(B, 2), 288>>>(x, out);
    k_gru<<<B, 192>>>(whh, bhh);
    k_cls<<<1, 256>>>(si, stw, stb, c1w, c1b, bng, bnb, c2w, c2b, out);
}